// round 1
// baseline (speedup 1.0000x reference)
#include <cuda_runtime.h>
#include <cstddef>

#define NATOMS 200000
#define MNBR   12
#define NEDGE  (NATOMS * MNBR)
#define FDIM   64
#define NBRF   41
#define ORIGF  92
#define NBATCH 2000
#define APC    100
#define HDIM   128
#define NCONVL 3

// ---- scratch (static device globals; no runtime allocation) ----
static __device__ float g_x [(size_t)NATOMS * FDIM];   // 51.2 MB
static __device__ float g_xw[(size_t)NATOMS * FDIM];   // 51.2 MB
static __device__ float g_r0[(size_t)NCONVL * NEDGE];  // 28.8 MB

// combined scale: c0 * alpha / M = 0.28209479177387814 * 0.125 / 12
#define AGG_SCALE 0.0029384874143112307f

__device__ __forceinline__ float softplus_f(float x) {
    // = jax.nn.softplus = logaddexp(x, 0), numerically stable form
    return fmaxf(x, 0.0f) + log1pf(__expf(-fabsf(x)));
}

// ============================================================================
// GEMM: C[rows x 64] = A[rows x K] @ W[K x 64] (+ bias). 64-row blocks,
// 16x16 threads, 4x4 microtile. K = 92 (embed) or 64 (conv).
// ============================================================================
template<int K, int KPAD>
__global__ void __launch_bounds__(256) gemm_kernel(
    const float* __restrict__ A, const float* __restrict__ W,
    const float* __restrict__ bias, float* __restrict__ C)
{
    __shared__ float sA[64][KPAD];   // KPAD odd -> conflict-free row reads
    __shared__ float sW[K][64];      // read as float4 along columns
    const int tx = threadIdx.x, ty = threadIdx.y;
    const int tid = ty * 16 + tx;
    const int rowBase = blockIdx.x * 64;

    for (int idx = tid; idx < 64 * K; idx += 256) {
        int r = idx / K, k = idx - r * K;
        sA[r][k] = A[(size_t)(rowBase + r) * K + k];
    }
    for (int idx = tid; idx < K * 64; idx += 256) {
        sW[idx >> 6][idx & 63] = W[idx];
    }
    __syncthreads();

    const int r0 = ty * 4, c0 = tx * 4;
    float acc[4][4];
    #pragma unroll
    for (int j = 0; j < 4; j++) {
        float b = bias ? bias[c0 + j] : 0.0f;
        acc[0][j] = b; acc[1][j] = b; acc[2][j] = b; acc[3][j] = b;
    }

    #pragma unroll 4
    for (int k = 0; k < K; k++) {
        float4 b4 = *(const float4*)&sW[k][c0];
        float a0 = sA[r0 + 0][k], a1 = sA[r0 + 1][k];
        float a2 = sA[r0 + 2][k], a3 = sA[r0 + 3][k];
        acc[0][0] += a0 * b4.x; acc[0][1] += a0 * b4.y; acc[0][2] += a0 * b4.z; acc[0][3] += a0 * b4.w;
        acc[1][0] += a1 * b4.x; acc[1][1] += a1 * b4.y; acc[1][2] += a1 * b4.z; acc[1][3] += a1 * b4.w;
        acc[2][0] += a2 * b4.x; acc[2][1] += a2 * b4.y; acc[2][2] += a2 * b4.z; acc[2][3] += a2 * b4.w;
        acc[3][0] += a3 * b4.x; acc[3][1] += a3 * b4.y; acc[3][2] += a3 * b4.z; acc[3][3] += a3 * b4.w;
    }

    #pragma unroll
    for (int i = 0; i < 4; i++) {
        float4 v = make_float4(acc[i][0], acc[i][1], acc[i][2], acc[i][3]);
        *(float4*)&C[(size_t)(rowBase + r0 + i) * 64 + c0] = v;
    }
}

// ============================================================================
// Edge-scalar kernel: for every edge and every layer l,
//   r0[l][e] = br2[l][0] + sum_j softplus( br1[l][j] + sum_i e_i * Wr1[l][i][j] ) * Wr2[l][j][0]
// One thread per edge; Wr1 (padded to 44 cols) in smem, broadcast float4 reads.
// ============================================================================
__global__ void __launch_bounds__(256) edge_kernel(
    const float* __restrict__ nbr_fea,
    const float* __restrict__ Wr1, const float* __restrict__ br1,
    const float* __restrict__ Wr2, const float* __restrict__ br2,
    float* __restrict__ r0out)
{
    __shared__ float sW [NCONVL][NBRF][44];
    __shared__ float sb1[NCONVL][44];
    __shared__ float sw2[NCONVL][44];
    __shared__ float sb2[NCONVL];
    const int tid = threadIdx.x;

    for (int idx = tid; idx < NCONVL * NBRF * NBRF; idx += 256) {
        int l = idx / (NBRF * NBRF);
        int r = idx - l * NBRF * NBRF;
        int i = r / NBRF, j = r - i * NBRF;
        sW[l][i][j] = Wr1[idx];
    }
    for (int idx = tid; idx < NCONVL * NBRF; idx += 256) {
        int l = idx / NBRF, i = idx - l * NBRF;
        sW[l][i][41] = 0.f; sW[l][i][42] = 0.f; sW[l][i][43] = 0.f;
        sb1[l][i] = br1[idx];
        sw2[l][i] = Wr2[idx * 9];          // Wr2[l][i][0], layout [3][41][9]
    }
    if (tid < NCONVL) {
        sb2[tid] = br2[tid * 9];           // br2[l][0], layout [3][9]
        sb1[tid][41] = sb1[tid][42] = sb1[tid][43] = 0.f;
        sw2[tid][41] = sw2[tid][42] = sw2[tid][43] = 0.f;
    }
    __syncthreads();

    const int eid = blockIdx.x * 256 + tid;       // NEDGE % 256 == 0
    float e[NBRF];
    const float* ep = nbr_fea + (size_t)eid * NBRF;
    #pragma unroll
    for (int i = 0; i < NBRF; i++) e[i] = ep[i];

    #pragma unroll 1
    for (int l = 0; l < NCONVL; l++) {
        float acc[44];
        #pragma unroll
        for (int j = 0; j < 44; j++) acc[j] = sb1[l][j];
        #pragma unroll
        for (int i = 0; i < NBRF; i++) {
            const float ei = e[i];
            const float4* w4 = (const float4*)sW[l][i];
            #pragma unroll
            for (int j = 0; j < 11; j++) {
                float4 w = w4[j];
                acc[4*j + 0] += ei * w.x;
                acc[4*j + 1] += ei * w.y;
                acc[4*j + 2] += ei * w.z;
                acc[4*j + 3] += ei * w.w;
            }
        }
        float r = sb2[l];
        #pragma unroll
        for (int j = 0; j < NBRF; j++)
            r += softplus_f(acc[j]) * sw2[l][j];
        r0out[(size_t)l * NEDGE + eid] = r;
    }
}

// ============================================================================
// Aggregate: x_new[n][f] = SCALE * sum_m r0[n*12+m] * xW[nbr_idx[n][m]][f]
// block = (64 feats, 4 atoms). xW fits in L2 -> gathers are L2 hits.
// ============================================================================
__global__ void __launch_bounds__(256) aggregate_kernel(
    const int* __restrict__ nbr_idx, const float* __restrict__ r0,
    const float* __restrict__ xw, float* __restrict__ xo)
{
    __shared__ int   sidx[4][MNBR];
    __shared__ float swt [4][MNBR];
    const int tx = threadIdx.x, ty = threadIdx.y;
    const int n = blockIdx.x * 4 + ty;
    if (tx < MNBR) {
        sidx[ty][tx] = nbr_idx[n * MNBR + tx];
        swt [ty][tx] = r0[(size_t)n * MNBR + tx];
    }
    __syncthreads();
    float acc = 0.f;
    #pragma unroll
    for (int m = 0; m < MNBR; m++)
        acc += swt[ty][m] * xw[(size_t)sidx[ty][m] * FDIM + tx];
    xo[(size_t)n * FDIM + tx] = acc * AGG_SCALE;
}

// ============================================================================
// Readout: crys = mean over 100 atoms; h = softplus(crys@W_fc + b_fc);
// out = h@W_out + b_out. Output layout: out[0..1999], then h[2000 x 128].
// ============================================================================
__global__ void __launch_bounds__(128) readout_kernel(
    const int* __restrict__ cidx, const float* __restrict__ x,
    const float* __restrict__ Wfc, const float* __restrict__ bfc,
    const float* __restrict__ Wout, const float* __restrict__ bout,
    float* __restrict__ out)
{
    __shared__ float crys[FDIM];
    __shared__ float red[HDIM];
    const int b = blockIdx.x, t = threadIdx.x;

    if (t < FDIM) {
        float s = 0.f;
        for (int a = 0; a < APC; a++) {
            int atom = cidx[b * APC + a];
            s += x[(size_t)atom * FDIM + t];
        }
        crys[t] = s * (1.0f / APC);
    }
    __syncthreads();

    float h = bfc[t];
    #pragma unroll 8
    for (int i = 0; i < FDIM; i++)
        h += crys[i] * Wfc[i * HDIM + t];
    h = softplus_f(h);
    out[NBATCH + (size_t)b * HDIM + t] = h;

    red[t] = h * Wout[t];
    __syncthreads();
    for (int s = HDIM / 2; s > 0; s >>= 1) {
        if (t < s) red[t] += red[t + s];
        __syncthreads();
    }
    if (t == 0) out[b] = red[0] + bout[0];
}

// ============================================================================
extern "C" void kernel_launch(void* const* d_in, const int* in_sizes, int n_in,
                              void* d_out, int out_size)
{
    const float* atom_fea = (const float*)d_in[0];
    const float* nbr_fea  = (const float*)d_in[1];
    const int*   nbr_idx  = (const int*)  d_in[2];
    const int*   cidx     = (const int*)  d_in[3];
    // d_in[4] = pos : provably unused (only Y[:,0] = constant is consumed)
    const float* W_emb = (const float*)d_in[5];
    const float* b_emb = (const float*)d_in[6];
    const float* Wr1   = (const float*)d_in[7];
    const float* br1   = (const float*)d_in[8];
    const float* Wr2   = (const float*)d_in[9];
    const float* br2   = (const float*)d_in[10];
    const float* Wtp   = (const float*)d_in[11];
    const float* Wfc   = (const float*)d_in[12];
    const float* bfc   = (const float*)d_in[13];
    const float* Wout  = (const float*)d_in[14];
    const float* bout  = (const float*)d_in[15];

    float *xp, *xwp, *r0p;
    cudaGetSymbolAddress((void**)&xp,  g_x);
    cudaGetSymbolAddress((void**)&xwp, g_xw);
    cudaGetSymbolAddress((void**)&r0p, g_r0);

    dim3 bg(16, 16);
    // x = atom_fea @ W_emb + b_emb
    gemm_kernel<ORIGF, 97><<<NATOMS / 64, bg>>>(atom_fea, W_emb, b_emb, xp);
    // all 3 layers' edge scalars in one pass over nbr_fea
    edge_kernel<<<NEDGE / 256, 256>>>(nbr_fea, Wr1, br1, Wr2, br2, r0p);
    // conv layers
    for (int l = 0; l < NCONVL; l++) {
        gemm_kernel<FDIM, 65><<<NATOMS / 64, bg>>>(xp, Wtp + l * FDIM * FDIM, nullptr, xwp);
        aggregate_kernel<<<NATOMS / 4, dim3(64, 4)>>>(nbr_idx, r0p + (size_t)l * NEDGE, xwp, xp);
    }
    // readout -> (out, h) flattened
    readout_kernel<<<NBATCH, 128>>>(cidx, xp, Wfc, bfc, Wout, bout, (float*)d_out);
}

// round 2
// speedup vs baseline: 1.2009x; 1.2009x over previous
#include <cuda_runtime.h>
#include <cstddef>

typedef unsigned long long ull;

#define NATOMS 200000
#define MNBR   12
#define NEDGE  (NATOMS * MNBR)
#define FDIM   64
#define NBRF   41
#define ORIGF  92
#define NBATCH 2000
#define APC    100
#define HDIM   128
#define NCONVL 3

// ---- scratch (static device globals; no runtime allocation) ----
static __device__ float g_x [(size_t)NATOMS * FDIM];   // 51.2 MB
static __device__ float g_xw[(size_t)NATOMS * FDIM];   // 51.2 MB
static __device__ float g_r0[(size_t)NCONVL * NEDGE];  // 28.8 MB

// combined scale: c0 * alpha / M = 0.28209479177387814 * 0.125 / 12
#define AGG_SCALE 0.0029384874143112307f

// ---- packed fp32x2 helpers (Blackwell FFMA2 path, PTX-only) ----
#define FMA2(acc, a, b) \
    asm("fma.rn.f32x2 %0, %1, %2, %0;" : "+l"(acc) : "l"(a), "l"(b))
#define DUP2(d, s) \
    asm("mov.b64 %0, {%1, %1};" : "=l"(d) : "f"(s))
#define PACK2(d, lo, hi) \
    asm("mov.b64 %0, {%1, %2};" : "=l"(d) : "f"(lo), "f"(hi))
#define UNPACK2(lo, hi, s) \
    asm("mov.b64 {%0, %1}, %2;" : "=f"(lo), "=f"(hi) : "l"(s))

// fast softplus contribution: r += max(x,0)*w2 + log2(1+2^(-x/ln2))*(w2*ln2)
__device__ __forceinline__ void sp_acc(float x, float w2, float w2ln, float& r) {
    float t = fabsf(x) * -1.442695041f;
    float ex; asm("ex2.approx.f32 %0, %1;" : "=f"(ex) : "f"(t));
    float lg; asm("lg2.approx.f32 %0, %1;" : "=f"(lg) : "f"(1.0f + ex));
    r = fmaf(fmaxf(x, 0.0f), w2, r);
    r = fmaf(lg, w2ln, r);
}

__device__ __forceinline__ float softplus_accurate(float x) {
    return fmaxf(x, 0.0f) + log1pf(__expf(-fabsf(x)));
}

// ============================================================================
// GEMM: C[rows x 64] = A[rows x K] @ W[K x 64] (+bias). 64-row blocks, 16x16
// threads, 4x4 microtile computed with packed f32x2 FMAs (column pairs).
// ============================================================================
template<int K, int KPAD>
__global__ void __launch_bounds__(256) gemm_kernel(
    const float* __restrict__ A, const float* __restrict__ W,
    const float* __restrict__ bias, float* __restrict__ C)
{
    __shared__ __align__(16) float sA[64][KPAD];   // KPAD odd -> conflict-free
    __shared__ __align__(16) float sW[K][64];
    const int tx = threadIdx.x, ty = threadIdx.y;
    const int tid = ty * 16 + tx;
    const int rowBase = blockIdx.x * 64;

    for (int idx = tid; idx < 64 * K; idx += 256) {
        int r = idx / K, k = idx - r * K;
        sA[r][k] = A[(size_t)(rowBase + r) * K + k];
    }
    for (int idx = tid; idx < K * 64; idx += 256)
        sW[idx >> 6][idx & 63] = W[idx];
    __syncthreads();

    const int r0 = ty * 4, c0 = tx * 4;
    ull acc[4][2];
    {
        float b0 = bias ? bias[c0 + 0] : 0.0f;
        float b1 = bias ? bias[c0 + 1] : 0.0f;
        float b2 = bias ? bias[c0 + 2] : 0.0f;
        float b3 = bias ? bias[c0 + 3] : 0.0f;
        ull p0, p1; PACK2(p0, b0, b1); PACK2(p1, b2, b3);
        #pragma unroll
        for (int i = 0; i < 4; i++) { acc[i][0] = p0; acc[i][1] = p1; }
    }

    #pragma unroll 4
    for (int k = 0; k < K; k++) {
        longlong2 w = *(const longlong2*)&sW[k][c0];  // (c0,c0+1)|(c0+2,c0+3)
        ull wa = (ull)w.x, wb = (ull)w.y;
        #pragma unroll
        for (int i = 0; i < 4; i++) {
            ull ad; DUP2(ad, sA[r0 + i][k]);
            FMA2(acc[i][0], ad, wa);
            FMA2(acc[i][1], ad, wb);
        }
    }

    #pragma unroll
    for (int i = 0; i < 4; i++) {
        float4 v;
        UNPACK2(v.x, v.y, acc[i][0]);
        UNPACK2(v.z, v.w, acc[i][1]);
        *(float4*)&C[(size_t)(rowBase + r0 + i) * 64 + c0] = v;
    }
}

// ============================================================================
// Edge-scalar kernel: for every edge and every layer l,
//   r0[l][e] = br2[l][0] + sum_j softplus( br1[l][j] + sum_i e_i*Wr1[l][i][j] )
//              * Wr2[l][j][0]
// nbr_fea staged through dynamic smem (coalesced), inner matvec in f32x2.
// ============================================================================
__global__ void __launch_bounds__(256) edge_kernel(
    const float* __restrict__ nbr_fea,
    const float* __restrict__ Wr1, const float* __restrict__ br1,
    const float* __restrict__ Wr2, const float* __restrict__ br2,
    float* __restrict__ r0out)
{
    __shared__ __align__(16) float sW   [NCONVL][NBRF][44];
    __shared__ __align__(16) float sb1  [NCONVL][44];
    __shared__ float sw2  [NCONVL][44];
    __shared__ float sw2ln[NCONVL][44];
    __shared__ float sb2  [NCONVL];
    extern __shared__ float se[];                 // 256*41 floats, staged edges
    const int tid = threadIdx.x;

    for (int idx = tid; idx < NCONVL * NBRF * NBRF; idx += 256) {
        int l = idx / (NBRF * NBRF);
        int r = idx - l * NBRF * NBRF;
        int i = r / NBRF, j = r - i * NBRF;
        sW[l][i][j] = Wr1[idx];
    }
    for (int idx = tid; idx < NCONVL * NBRF; idx += 256) {
        int l = idx / NBRF, i = idx - l * NBRF;
        sW[l][i][41] = 0.f; sW[l][i][42] = 0.f; sW[l][i][43] = 0.f;
        sb1[l][i]   = br1[idx];
        float w2    = Wr2[idx * 9];               // Wr2[l][i][0], layout [3][41][9]
        sw2[l][i]   = w2;
        sw2ln[l][i] = w2 * 0.6931471805599453f;
    }
    if (tid < NCONVL) {
        sb2[tid] = br2[tid * 9];                  // br2[l][0], layout [3][9]
        sb1[tid][41] = sb1[tid][42] = sb1[tid][43] = 0.f;
        sw2[tid][41] = sw2[tid][42] = sw2[tid][43] = 0.f;
        sw2ln[tid][41] = sw2ln[tid][42] = sw2ln[tid][43] = 0.f;
    }

    // coalesced stage of this block's 256 edges (256*41 floats, 16B aligned)
    {
        const float4* src = (const float4*)(nbr_fea + (size_t)blockIdx.x * 256 * NBRF);
        float4* dst = (float4*)se;
        for (int k = tid; k < 256 * NBRF / 4; k += 256) dst[k] = src[k];
    }
    __syncthreads();

    // copy own edge features to registers (stride 41 -> conflict-free LDS)
    float e[NBRF];
    #pragma unroll
    for (int i = 0; i < NBRF; i++) e[i] = se[tid * NBRF + i];

    const int eid = blockIdx.x * 256 + tid;       // NEDGE % 256 == 0

    #pragma unroll 1
    for (int l = 0; l < NCONVL; l++) {
        ull acc[22];
        {
            const longlong2* bp = (const longlong2*)sb1[l];
            #pragma unroll
            for (int j = 0; j < 11; j++) {
                longlong2 v = bp[j];
                acc[2*j] = (ull)v.x; acc[2*j+1] = (ull)v.y;
            }
        }
        #pragma unroll
        for (int i = 0; i < NBRF; i++) {
            ull ai; DUP2(ai, e[i]);
            const longlong2* wp = (const longlong2*)sW[l][i];
            #pragma unroll
            for (int j = 0; j < 11; j++) {
                longlong2 w = wp[j];
                ull wa = (ull)w.x, wb = (ull)w.y;
                FMA2(acc[2*j],   ai, wa);
                FMA2(acc[2*j+1], ai, wb);
            }
        }
        float r = sb2[l];
        #pragma unroll
        for (int j = 0; j < 21; j++) {            // cols 0..41 carry weight
            float lo, hi; UNPACK2(lo, hi, acc[j]);
            sp_acc(lo, sw2[l][2*j],   sw2ln[l][2*j],   r);
            sp_acc(hi, sw2[l][2*j+1], sw2ln[l][2*j+1], r);
        }
        r0out[(size_t)l * NEDGE + eid] = r;
    }
}

// ============================================================================
// Aggregate: x_new[n][f] = SCALE * sum_m r0[n*12+m] * xW[nbr_idx[n][m]][f]
// block = 16 atoms x 16 threads, float4 per thread; xW is L2-resident.
// ============================================================================
__global__ void __launch_bounds__(256) aggregate_kernel(
    const int* __restrict__ nbr_idx, const float* __restrict__ r0,
    const float* __restrict__ xw, float* __restrict__ xo)
{
    __shared__ int   sidx[16][MNBR];
    __shared__ float swt [16][MNBR];
    const int tx = threadIdx.x, ty = threadIdx.y;
    const int tid = ty * 16 + tx;
    const int nBase = blockIdx.x * 16;
    if (tid < 16 * MNBR) {
        int a = tid / MNBR, m = tid - a * MNBR;
        sidx[a][m] = nbr_idx[(size_t)(nBase + a) * MNBR + m];
        swt [a][m] = r0[(size_t)(nBase + a) * MNBR + m];
    }
    __syncthreads();

    ull a0 = 0, a1 = 0;
    #pragma unroll
    for (int m = 0; m < MNBR; m++) {
        const longlong2 v = *(const longlong2*)
            &xw[(size_t)sidx[ty][m] * FDIM + tx * 4];
        ull wd; DUP2(wd, swt[ty][m]);
        ull va = (ull)v.x, vb = (ull)v.y;
        FMA2(a0, wd, va);
        FMA2(a1, wd, vb);
    }
    float4 o;
    UNPACK2(o.x, o.y, a0);
    UNPACK2(o.z, o.w, a1);
    o.x *= AGG_SCALE; o.y *= AGG_SCALE; o.z *= AGG_SCALE; o.w *= AGG_SCALE;
    *(float4*)&xo[(size_t)(nBase + ty) * FDIM + tx * 4] = o;
}

// ============================================================================
// Readout: crys = mean over 100 atoms; h = softplus(crys@W_fc + b_fc);
// out = h@W_out + b_out. Output layout: out[0..1999], then h[2000 x 128].
// ============================================================================
__global__ void __launch_bounds__(128) readout_kernel(
    const int* __restrict__ cidx, const float* __restrict__ x,
    const float* __restrict__ Wfc, const float* __restrict__ bfc,
    const float* __restrict__ Wout, const float* __restrict__ bout,
    float* __restrict__ out)
{
    __shared__ float crys[FDIM];
    __shared__ float red[HDIM];
    const int b = blockIdx.x, t = threadIdx.x;

    if (t < FDIM) {
        float s = 0.f;
        for (int a = 0; a < APC; a++) {
            int atom = cidx[b * APC + a];
            s += x[(size_t)atom * FDIM + t];
        }
        crys[t] = s * (1.0f / APC);
    }
    __syncthreads();

    float h = bfc[t];
    #pragma unroll 8
    for (int i = 0; i < FDIM; i++)
        h += crys[i] * Wfc[i * HDIM + t];
    h = softplus_accurate(h);
    out[NBATCH + (size_t)b * HDIM + t] = h;

    red[t] = h * Wout[t];
    __syncthreads();
    for (int s = HDIM / 2; s > 0; s >>= 1) {
        if (t < s) red[t] += red[t + s];
        __syncthreads();
    }
    if (t == 0) out[b] = red[0] + bout[0];
}

// ============================================================================
extern "C" void kernel_launch(void* const* d_in, const int* in_sizes, int n_in,
                              void* d_out, int out_size)
{
    const float* atom_fea = (const float*)d_in[0];
    const float* nbr_fea  = (const float*)d_in[1];
    const int*   nbr_idx  = (const int*)  d_in[2];
    const int*   cidx     = (const int*)  d_in[3];
    // d_in[4] = pos : provably unused (only Y[:,0] = constant is consumed)
    const float* W_emb = (const float*)d_in[5];
    const float* b_emb = (const float*)d_in[6];
    const float* Wr1   = (const float*)d_in[7];
    const float* br1   = (const float*)d_in[8];
    const float* Wr2   = (const float*)d_in[9];
    const float* br2   = (const float*)d_in[10];
    const float* Wtp   = (const float*)d_in[11];
    const float* Wfc   = (const float*)d_in[12];
    const float* bfc   = (const float*)d_in[13];
    const float* Wout  = (const float*)d_in[14];
    const float* bout  = (const float*)d_in[15];

    float *xp, *xwp, *r0p;
    cudaGetSymbolAddress((void**)&xp,  g_x);
    cudaGetSymbolAddress((void**)&xwp, g_xw);
    cudaGetSymbolAddress((void**)&r0p, g_r0);

    const int edgeSmem = 256 * NBRF * (int)sizeof(float);   // 41984 B
    static bool attrSet = false;
    if (!attrSet) {
        cudaFuncSetAttribute(edge_kernel,
            cudaFuncAttributeMaxDynamicSharedMemorySize, edgeSmem);
        attrSet = true;
    }

    dim3 bg(16, 16);
    // x = atom_fea @ W_emb + b_emb
    gemm_kernel<ORIGF, 97><<<NATOMS / 64, bg>>>(atom_fea, W_emb, b_emb, xp);
    // all 3 layers' edge scalars in one pass over nbr_fea
    edge_kernel<<<NEDGE / 256, 256, edgeSmem>>>(nbr_fea, Wr1, br1, Wr2, br2, r0p);
    // conv layers
    for (int l = 0; l < NCONVL; l++) {
        gemm_kernel<FDIM, 65><<<NATOMS / 64, bg>>>(xp, Wtp + l * FDIM * FDIM, nullptr, xwp);
        aggregate_kernel<<<NATOMS / 16, dim3(16, 16)>>>(nbr_idx, r0p + (size_t)l * NEDGE, xwp, xp);
    }
    // readout -> (out, h) flattened
    readout_kernel<<<NBATCH, 128>>>(cidx, xp, Wfc, bfc, Wout, bout, (float*)d_out);
}